// round 5
// baseline (speedup 1.0000x reference)
#include <cuda_runtime.h>

// Problem constants (fixed by setup_inputs)
#define B_    8
#define LQ_   2048
#define LKV_  1024
#define DM    1024
#define IM    512
#define H_    16
#define DK_   64

// ---------------------------------------------------------------------------
// Scratch (device globals; no allocation allowed)
// ---------------------------------------------------------------------------
__device__ float g_Qp[(size_t)B_ * LQ_ * DM];   // projected Q  [B*LQ, 1024]
__device__ float g_Kp[(size_t)B_ * LKV_ * DM];  // projected K  [B*LKV, 1024]
__device__ float g_Vp[(size_t)B_ * LKV_ * DM];  // projected V  [B*LKV, 1024]
__device__ float g_Ao[(size_t)B_ * LQ_ * DM];   // attention out (concat layout)

// ---------------------------------------------------------------------------
// GEMM + bias:  C[M,N] = A[M,K] @ W[K,N] + bias[N]
// 128x128x16 tiles, 256 threads, 8x8 per-thread register tile,
// register prefetch of next K-tile.
// Requires M%128==0, N%128==0, K%16==0 (true for all our shapes).
// ---------------------------------------------------------------------------
__global__ __launch_bounds__(256)
void gemm_bias_kernel(const float* __restrict__ A,
                      const float* __restrict__ W,
                      const float* __restrict__ bias,
                      float* __restrict__ C,
                      int M, int N, int K)
{
    __shared__ float As[16][132];   // A tile transposed [k][m], +4 pad
    __shared__ float Bs[16][128];   // W tile natural    [k][n]

    const int tid = threadIdx.x;
    const int tx  = tid & 15;       // 0..15 -> 8 cols each
    const int ty  = tid >> 4;       // 0..15 -> 8 rows each

    const int n0 = blockIdx.x * 128;
    const int m0 = blockIdx.y * 128;

    const float* Ab = A + (size_t)m0 * K;
    const float* Wb = W + n0;

    // Load mapping
    const int arow = tid >> 2;          // 0..63
    const int ak4  = (tid & 3) * 4;     // 0,4,8,12
    const int bk   = tid >> 5;          // 0..7
    const int bn4  = (tid & 31) * 4;    // 0..124

    float4 ra0, ra1, rb0, rb1;

    // prefetch tile 0
    ra0 = *(const float4*)(Ab + (size_t)arow       * K + ak4);
    ra1 = *(const float4*)(Ab + (size_t)(arow + 64) * K + ak4);
    rb0 = *(const float4*)(Wb + (size_t)bk       * N + bn4);
    rb1 = *(const float4*)(Wb + (size_t)(bk + 8) * N + bn4);

    float acc[8][8];
#pragma unroll
    for (int i = 0; i < 8; ++i)
#pragma unroll
        for (int j = 0; j < 8; ++j) acc[i][j] = 0.f;

    const int T = K / 16;
    for (int t = 0; t < T; ++t) {
        // store prefetched tile to smem
        As[ak4 + 0][arow]      = ra0.x;
        As[ak4 + 1][arow]      = ra0.y;
        As[ak4 + 2][arow]      = ra0.z;
        As[ak4 + 3][arow]      = ra0.w;
        As[ak4 + 0][arow + 64] = ra1.x;
        As[ak4 + 1][arow + 64] = ra1.y;
        As[ak4 + 2][arow + 64] = ra1.z;
        As[ak4 + 3][arow + 64] = ra1.w;
        *(float4*)&Bs[bk][bn4]     = rb0;
        *(float4*)&Bs[bk + 8][bn4] = rb1;
        __syncthreads();

        // prefetch next tile (global loads overlap compute)
        if (t + 1 < T) {
            const int k0 = (t + 1) * 16;
            ra0 = *(const float4*)(Ab + (size_t)arow       * K + k0 + ak4);
            ra1 = *(const float4*)(Ab + (size_t)(arow + 64) * K + k0 + ak4);
            rb0 = *(const float4*)(Wb + (size_t)(k0 + bk)     * N + bn4);
            rb1 = *(const float4*)(Wb + (size_t)(k0 + bk + 8) * N + bn4);
        }

        float a[8], bb[8];
#pragma unroll
        for (int kk = 0; kk < 16; ++kk) {
            *(float4*)&a[0]  = *(const float4*)&As[kk][ty * 8];
            *(float4*)&a[4]  = *(const float4*)&As[kk][ty * 8 + 4];
            *(float4*)&bb[0] = *(const float4*)&Bs[kk][tx * 8];
            *(float4*)&bb[4] = *(const float4*)&Bs[kk][tx * 8 + 4];
#pragma unroll
            for (int i = 0; i < 8; ++i)
#pragma unroll
                for (int j = 0; j < 8; ++j)
                    acc[i][j] = fmaf(a[i], bb[j], acc[i][j]);
        }
        __syncthreads();
    }

    // epilogue: bias + store
    const int crow = m0 + ty * 8;
    const int ccol = n0 + tx * 8;
    float bv[8];
#pragma unroll
    for (int j = 0; j < 8; ++j) bv[j] = bias[ccol + j];

#pragma unroll
    for (int i = 0; i < 8; ++i) {
        float4 o0, o1;
        o0.x = acc[i][0] + bv[0];
        o0.y = acc[i][1] + bv[1];
        o0.z = acc[i][2] + bv[2];
        o0.w = acc[i][3] + bv[3];
        o1.x = acc[i][4] + bv[4];
        o1.y = acc[i][5] + bv[5];
        o1.z = acc[i][6] + bv[6];
        o1.w = acc[i][7] + bv[7];
        float* cp = C + (size_t)(crow + i) * N + ccol;
        *(float4*)cp       = o0;
        *(float4*)(cp + 4) = o1;
    }
}

// ---------------------------------------------------------------------------
// Fused flash attention per (b, h, 64-row q-tile).
// Layouts: Qp/Kp/Vp are [B*L, 1024]; head h occupies cols h*64..h*64+63.
// Output written to g_Ao in concat layout [B*LQ, 1024].
// ---------------------------------------------------------------------------
#define QPAD 68
// XOR-swizzled K^T store: element (d, kv) of the 64x64 tile
#define KIDX(d, kv) ((d) * 64 + (((((kv) >> 2) ^ ((d) >> 2)) & 15) << 2) + ((kv) & 3))

#define SMEM_ATTN_FLOATS (64*QPAD /*Qs*/ + 64*64 /*Ks*/ + 64*QPAD /*Vs*/ + 64*QPAD /*Ss*/ + 3*64)
#define SMEM_ATTN_BYTES  (SMEM_ATTN_FLOATS * 4)

__global__ __launch_bounds__(256)
void attn_kernel(const float* __restrict__ Qp,
                 const float* __restrict__ Kp,
                 const float* __restrict__ Vp,
                 float* __restrict__ Ao)
{
    extern __shared__ float sm[];
    float* Qs  = sm;                    // [64][QPAD], pre-scaled by 1/8
    float* Ks  = Qs + 64 * QPAD;        // swizzled K^T: [d][kv]
    float* Vs  = Ks + 64 * 64;          // [kv][QPAD]
    float* Ss  = Vs + 64 * QPAD;        // scores / probs [row][QPAD]
    float* m_s = Ss + 64 * QPAD;        // running max  [64]
    float* l_s = m_s + 64;              // running sum  [64]
    float* c_s = l_s + 64;              // per-tile rescale [64]

    const int tid  = threadIdx.x;
    const int tx   = tid & 15;          // 0..15 : 4 cols each
    const int ty   = tid >> 4;          // 0..15 : 4 rows each
    const int lane = tid & 31;
    const int wrp  = tid >> 5;

    const int h  = blockIdx.y;
    const int b  = blockIdx.z;
    const int q0 = blockIdx.x * 64;

    const float* Qg = Qp + ((size_t)(b * LQ_ + q0)) * DM + h * DK_;
    const float* Kg = Kp + ((size_t)b * LKV_) * DM + h * DK_;
    const float* Vg = Vp + ((size_t)b * LKV_) * DM + h * DK_;

    const float scale = 0.125f;  // 1/sqrt(64)

    // load Q tile (scaled)
    {
        const int d4 = (tid & 15) * 4;
        const int r0 = tid >> 4;
#pragma unroll
        for (int p = 0; p < 4; ++p) {
            const int row = r0 + p * 16;
            float4 v = *(const float4*)(Qg + (size_t)row * DM + d4);
            v.x *= scale; v.y *= scale; v.z *= scale; v.w *= scale;
            *(float4*)(Qs + row * QPAD + d4) = v;
        }
    }
    if (tid < 64) { m_s[tid] = -1e30f; l_s[tid] = 0.f; }

    float o[4][4];
#pragma unroll
    for (int i = 0; i < 4; ++i)
#pragma unroll
        for (int j = 0; j < 4; ++j) o[i][j] = 0.f;

    const int ntiles = LKV_ / 64;
    for (int t = 0; t < ntiles; ++t) {
        __syncthreads();  // guard smem reuse from previous iteration

        // load K (swizzled transpose) and V (natural) tiles
        {
            const int d4 = (tid & 15) * 4;
            const int k0 = tid >> 4;
#pragma unroll
            for (int p = 0; p < 4; ++p) {
                const int kv = k0 + p * 16;
                const size_t goff = (size_t)(t * 64 + kv) * DM + d4;
                float4 kvv = *(const float4*)(Kg + goff);
                Ks[KIDX(d4 + 0, kv)] = kvv.x;
                Ks[KIDX(d4 + 1, kv)] = kvv.y;
                Ks[KIDX(d4 + 2, kv)] = kvv.z;
                Ks[KIDX(d4 + 3, kv)] = kvv.w;
                float4 vvv = *(const float4*)(Vg + goff);
                *(float4*)(Vs + kv * QPAD + d4) = vvv;
            }
        }
        __syncthreads();

        // S = Q @ K^T  (per-thread 4x4)
        float s[4][4];
#pragma unroll
        for (int i = 0; i < 4; ++i)
#pragma unroll
            for (int j = 0; j < 4; ++j) s[i][j] = 0.f;

#pragma unroll 8
        for (int dd = 0; dd < 64; ++dd) {
            float a0 = Qs[(4 * ty + 0) * QPAD + dd];
            float a1 = Qs[(4 * ty + 1) * QPAD + dd];
            float a2 = Qs[(4 * ty + 2) * QPAD + dd];
            float a3 = Qs[(4 * ty + 3) * QPAD + dd];
            float4 bb = *(const float4*)(Ks + dd * 64 + (((tx ^ (dd >> 2)) & 15) << 2));
            s[0][0] = fmaf(a0, bb.x, s[0][0]); s[0][1] = fmaf(a0, bb.y, s[0][1]);
            s[0][2] = fmaf(a0, bb.z, s[0][2]); s[0][3] = fmaf(a0, bb.w, s[0][3]);
            s[1][0] = fmaf(a1, bb.x, s[1][0]); s[1][1] = fmaf(a1, bb.y, s[1][1]);
            s[1][2] = fmaf(a1, bb.z, s[1][2]); s[1][3] = fmaf(a1, bb.w, s[1][3]);
            s[2][0] = fmaf(a2, bb.x, s[2][0]); s[2][1] = fmaf(a2, bb.y, s[2][1]);
            s[2][2] = fmaf(a2, bb.z, s[2][2]); s[2][3] = fmaf(a2, bb.w, s[2][3]);
            s[3][0] = fmaf(a3, bb.x, s[3][0]); s[3][1] = fmaf(a3, bb.y, s[3][1]);
            s[3][2] = fmaf(a3, bb.z, s[3][2]); s[3][3] = fmaf(a3, bb.w, s[3][3]);
        }
#pragma unroll
        for (int i = 0; i < 4; ++i) {
            float4 sv = make_float4(s[i][0], s[i][1], s[i][2], s[i][3]);
            *(float4*)(Ss + (4 * ty + i) * QPAD + 4 * tx) = sv;
        }
        __syncthreads();

        // online softmax: each warp owns 8 rows
#pragma unroll
        for (int rr = 0; rr < 8; ++rr) {
            const int row = wrp * 8 + rr;
            float v0 = Ss[row * QPAD + lane];
            float v1 = Ss[row * QPAD + 32 + lane];
            float mx = fmaxf(v0, v1);
#pragma unroll
            for (int off = 16; off > 0; off >>= 1)
                mx = fmaxf(mx, __shfl_xor_sync(0xffffffffu, mx, off));
            const float mold = m_s[row];
            const float mnew = fmaxf(mold, mx);
            const float p0 = __expf(v0 - mnew);
            const float p1 = __expf(v1 - mnew);
            Ss[row * QPAD + lane]      = p0;
            Ss[row * QPAD + 32 + lane] = p1;
            float sum = p0 + p1;
#pragma unroll
            for (int off = 16; off > 0; off >>= 1)
                sum += __shfl_xor_sync(0xffffffffu, sum, off);
            if (lane == 0) {
                const float c = __expf(mold - mnew);
                c_s[row] = c;
                l_s[row] = l_s[row] * c + sum;
                m_s[row] = mnew;
            }
        }
        __syncthreads();

        // rescale O and accumulate P @ V
        {
            const float c0 = c_s[4 * ty + 0];
            const float c1 = c_s[4 * ty + 1];
            const float c2 = c_s[4 * ty + 2];
            const float c3 = c_s[4 * ty + 3];
#pragma unroll
            for (int j = 0; j < 4; ++j) {
                o[0][j] *= c0; o[1][j] *= c1; o[2][j] *= c2; o[3][j] *= c3;
            }
        }
#pragma unroll 8
        for (int k = 0; k < 64; ++k) {
            float a0 = Ss[(4 * ty + 0) * QPAD + k];
            float a1 = Ss[(4 * ty + 1) * QPAD + k];
            float a2 = Ss[(4 * ty + 2) * QPAD + k];
            float a3 = Ss[(4 * ty + 3) * QPAD + k];
            float4 bb = *(const float4*)(Vs + k * QPAD + 4 * tx);
            o[0][0] = fmaf(a0, bb.x, o[0][0]); o[0][1] = fmaf(a0, bb.y, o[0][1]);
            o[0][2] = fmaf(a0, bb.z, o[0][2]); o[0][3] = fmaf(a0, bb.w, o[0][3]);
            o[1][0] = fmaf(a1, bb.x, o[1][0]); o[1][1] = fmaf(a1, bb.y, o[1][1]);
            o[1][2] = fmaf(a1, bb.z, o[1][2]); o[1][3] = fmaf(a1, bb.w, o[1][3]);
            o[2][0] = fmaf(a2, bb.x, o[2][0]); o[2][1] = fmaf(a2, bb.y, o[2][1]);
            o[2][2] = fmaf(a2, bb.z, o[2][2]); o[2][3] = fmaf(a2, bb.w, o[2][3]);
            o[3][0] = fmaf(a3, bb.x, o[3][0]); o[3][1] = fmaf(a3, bb.y, o[3][1]);
            o[3][2] = fmaf(a3, bb.z, o[3][2]); o[3][3] = fmaf(a3, bb.w, o[3][3]);
        }
    }

    // epilogue: normalize and write concat layout
#pragma unroll
    for (int i = 0; i < 4; ++i) {
        const int r   = 4 * ty + i;
        const float inv = 1.0f / l_s[r];
        float4 ov = make_float4(o[i][0] * inv, o[i][1] * inv,
                                o[i][2] * inv, o[i][3] * inv);
        *(float4*)(Ao + ((size_t)(b * LQ_ + q0 + r)) * DM + h * DK_ + 4 * tx) = ov;
    }
}

// ---------------------------------------------------------------------------
// Launch
// ---------------------------------------------------------------------------
extern "C" void kernel_launch(void* const* d_in, const int* in_sizes, int n_in,
                              void* d_out, int out_size)
{
    const float* q  = (const float*)d_in[0];
    const float* k  = (const float*)d_in[1];
    const float* v  = (const float*)d_in[2];
    const float* Wq = (const float*)d_in[3];
    const float* bq = (const float*)d_in[4];
    const float* Wk = (const float*)d_in[5];
    const float* bk = (const float*)d_in[6];
    const float* Wv = (const float*)d_in[7];
    const float* bv = (const float*)d_in[8];
    const float* Wo = (const float*)d_in[9];
    const float* bo = (const float*)d_in[10];
    float* out = (float*)d_out;

    float *Qp, *Kp, *Vp, *Ao;
    cudaGetSymbolAddress((void**)&Qp, g_Qp);
    cudaGetSymbolAddress((void**)&Kp, g_Kp);
    cudaGetSymbolAddress((void**)&Vp, g_Vp);
    cudaGetSymbolAddress((void**)&Ao, g_Ao);

    cudaFuncSetAttribute(attn_kernel,
                         cudaFuncAttributeMaxDynamicSharedMemorySize,
                         SMEM_ATTN_BYTES);

    const dim3 blk(256);

    // Q projection: [16384,1024] = q @ Wq + bq
    gemm_bias_kernel<<<dim3(DM / 128, (B_ * LQ_) / 128), blk>>>(
        q, Wq, bq, Qp, B_ * LQ_, DM, DM);
    // K projection: [8192,1024] = k @ Wk + bk   (K-dim = 512)
    gemm_bias_kernel<<<dim3(DM / 128, (B_ * LKV_) / 128), blk>>>(
        k, Wk, bk, Kp, B_ * LKV_, DM, IM);
    // V projection
    gemm_bias_kernel<<<dim3(DM / 128, (B_ * LKV_) / 128), blk>>>(
        v, Wv, bv, Vp, B_ * LKV_, DM, IM);

    // fused attention -> concat layout
    attn_kernel<<<dim3(LQ_ / 64, H_, B_), blk, SMEM_ATTN_BYTES>>>(Qp, Kp, Vp, Ao);

    // output projection -> d_out
    gemm_bias_kernel<<<dim3(DM / 128, (B_ * LQ_) / 128), blk>>>(
        Ao, Wo, bo, out, B_ * LQ_, DM, DM);
}

// round 6
// speedup vs baseline: 1.0003x; 1.0003x over previous
#include <cuda_runtime.h>

// Problem constants (fixed by setup_inputs)
#define B_    8
#define LQ_   2048
#define LKV_  1024
#define DM    1024
#define IM    512
#define H_    16
#define DK_   64

// ---------------------------------------------------------------------------
// Scratch (device globals; no allocation allowed)
// ---------------------------------------------------------------------------
__device__ float g_Qp[(size_t)B_ * LQ_ * DM];   // projected Q  [B*LQ, 1024]
__device__ float g_Kp[(size_t)B_ * LKV_ * DM];  // projected K  [B*LKV, 1024]
__device__ float g_Vp[(size_t)B_ * LKV_ * DM];  // projected V  [B*LKV, 1024]
__device__ float g_Ao[(size_t)B_ * LQ_ * DM];   // attention out (concat layout)

// ---------------------------------------------------------------------------
// GEMM + bias:  C[M,N] = A[M,K] @ W[K,N] + bias[N]
// 128x128x16 tiles, 256 threads, 8x8 per-thread register tile,
// register prefetch of next K-tile.
// Requires M%128==0, N%128==0, K%16==0 (true for all our shapes).
// ---------------------------------------------------------------------------
__global__ __launch_bounds__(256)
void gemm_bias_kernel(const float* __restrict__ A,
                      const float* __restrict__ W,
                      const float* __restrict__ bias,
                      float* __restrict__ C,
                      int M, int N, int K)
{
    __shared__ float As[16][132];   // A tile transposed [k][m], +4 pad
    __shared__ float Bs[16][128];   // W tile natural    [k][n]

    const int tid = threadIdx.x;
    const int tx  = tid & 15;       // 0..15 -> 8 cols each
    const int ty  = tid >> 4;       // 0..15 -> 8 rows each

    const int n0 = blockIdx.x * 128;
    const int m0 = blockIdx.y * 128;

    const float* Ab = A + (size_t)m0 * K;
    const float* Wb = W + n0;

    // Load mapping
    const int arow = tid >> 2;          // 0..63
    const int ak4  = (tid & 3) * 4;     // 0,4,8,12
    const int bk   = tid >> 5;          // 0..7
    const int bn4  = (tid & 31) * 4;    // 0..124

    float4 ra0, ra1, rb0, rb1;

    // prefetch tile 0
    ra0 = *(const float4*)(Ab + (size_t)arow       * K + ak4);
    ra1 = *(const float4*)(Ab + (size_t)(arow + 64) * K + ak4);
    rb0 = *(const float4*)(Wb + (size_t)bk       * N + bn4);
    rb1 = *(const float4*)(Wb + (size_t)(bk + 8) * N + bn4);

    float acc[8][8];
#pragma unroll
    for (int i = 0; i < 8; ++i)
#pragma unroll
        for (int j = 0; j < 8; ++j) acc[i][j] = 0.f;

    const int T = K / 16;
    for (int t = 0; t < T; ++t) {
        // store prefetched tile to smem
        As[ak4 + 0][arow]      = ra0.x;
        As[ak4 + 1][arow]      = ra0.y;
        As[ak4 + 2][arow]      = ra0.z;
        As[ak4 + 3][arow]      = ra0.w;
        As[ak4 + 0][arow + 64] = ra1.x;
        As[ak4 + 1][arow + 64] = ra1.y;
        As[ak4 + 2][arow + 64] = ra1.z;
        As[ak4 + 3][arow + 64] = ra1.w;
        *(float4*)&Bs[bk][bn4]     = rb0;
        *(float4*)&Bs[bk + 8][bn4] = rb1;
        __syncthreads();

        // prefetch next tile (global loads overlap compute)
        if (t + 1 < T) {
            const int k0 = (t + 1) * 16;
            ra0 = *(const float4*)(Ab + (size_t)arow       * K + k0 + ak4);
            ra1 = *(const float4*)(Ab + (size_t)(arow + 64) * K + k0 + ak4);
            rb0 = *(const float4*)(Wb + (size_t)(k0 + bk)     * N + bn4);
            rb1 = *(const float4*)(Wb + (size_t)(k0 + bk + 8) * N + bn4);
        }

        float a[8], bb[8];
#pragma unroll
        for (int kk = 0; kk < 16; ++kk) {
            *(float4*)&a[0]  = *(const float4*)&As[kk][ty * 8];
            *(float4*)&a[4]  = *(const float4*)&As[kk][ty * 8 + 4];
            *(float4*)&bb[0] = *(const float4*)&Bs[kk][tx * 8];
            *(float4*)&bb[4] = *(const float4*)&Bs[kk][tx * 8 + 4];
#pragma unroll
            for (int i = 0; i < 8; ++i)
#pragma unroll
                for (int j = 0; j < 8; ++j)
                    acc[i][j] = fmaf(a[i], bb[j], acc[i][j]);
        }
        __syncthreads();
    }

    // epilogue: bias + store
    const int crow = m0 + ty * 8;
    const int ccol = n0 + tx * 8;
    float bv[8];
#pragma unroll
    for (int j = 0; j < 8; ++j) bv[j] = bias[ccol + j];

#pragma unroll
    for (int i = 0; i < 8; ++i) {
        float4 o0, o1;
        o0.x = acc[i][0] + bv[0];
        o0.y = acc[i][1] + bv[1];
        o0.z = acc[i][2] + bv[2];
        o0.w = acc[i][3] + bv[3];
        o1.x = acc[i][4] + bv[4];
        o1.y = acc[i][5] + bv[5];
        o1.z = acc[i][6] + bv[6];
        o1.w = acc[i][7] + bv[7];
        float* cp = C + (size_t)(crow + i) * N + ccol;
        *(float4*)cp       = o0;
        *(float4*)(cp + 4) = o1;
    }
}

// ---------------------------------------------------------------------------
// Fused flash attention per (b, h, 64-row q-tile).
// Layouts: Qp/Kp/Vp are [B*L, 1024]; head h occupies cols h*64..h*64+63.
// Output written to g_Ao in concat layout [B*LQ, 1024].
// ---------------------------------------------------------------------------
#define QPAD 68
// XOR-swizzled K^T store: element (d, kv) of the 64x64 tile
#define KIDX(d, kv) ((d) * 64 + (((((kv) >> 2) ^ ((d) >> 2)) & 15) << 2) + ((kv) & 3))

#define SMEM_ATTN_FLOATS (64*QPAD /*Qs*/ + 64*64 /*Ks*/ + 64*QPAD /*Vs*/ + 64*QPAD /*Ss*/ + 3*64)
#define SMEM_ATTN_BYTES  (SMEM_ATTN_FLOATS * 4)

__global__ __launch_bounds__(256)
void attn_kernel(const float* __restrict__ Qp,
                 const float* __restrict__ Kp,
                 const float* __restrict__ Vp,
                 float* __restrict__ Ao)
{
    extern __shared__ float sm[];
    float* Qs  = sm;                    // [64][QPAD], pre-scaled by 1/8
    float* Ks  = Qs + 64 * QPAD;        // swizzled K^T: [d][kv]
    float* Vs  = Ks + 64 * 64;          // [kv][QPAD]
    float* Ss  = Vs + 64 * QPAD;        // scores / probs [row][QPAD]
    float* m_s = Ss + 64 * QPAD;        // running max  [64]
    float* l_s = m_s + 64;              // running sum  [64]
    float* c_s = l_s + 64;              // per-tile rescale [64]

    const int tid  = threadIdx.x;
    const int tx   = tid & 15;          // 0..15 : 4 cols each
    const int ty   = tid >> 4;          // 0..15 : 4 rows each
    const int lane = tid & 31;
    const int wrp  = tid >> 5;

    const int h  = blockIdx.y;
    const int b  = blockIdx.z;
    const int q0 = blockIdx.x * 64;

    const float* Qg = Qp + ((size_t)(b * LQ_ + q0)) * DM + h * DK_;
    const float* Kg = Kp + ((size_t)b * LKV_) * DM + h * DK_;
    const float* Vg = Vp + ((size_t)b * LKV_) * DM + h * DK_;

    const float scale = 0.125f;  // 1/sqrt(64)

    // load Q tile (scaled)
    {
        const int d4 = (tid & 15) * 4;
        const int r0 = tid >> 4;
#pragma unroll
        for (int p = 0; p < 4; ++p) {
            const int row = r0 + p * 16;
            float4 v = *(const float4*)(Qg + (size_t)row * DM + d4);
            v.x *= scale; v.y *= scale; v.z *= scale; v.w *= scale;
            *(float4*)(Qs + row * QPAD + d4) = v;
        }
    }
    if (tid < 64) { m_s[tid] = -1e30f; l_s[tid] = 0.f; }

    float o[4][4];
#pragma unroll
    for (int i = 0; i < 4; ++i)
#pragma unroll
        for (int j = 0; j < 4; ++j) o[i][j] = 0.f;

    const int ntiles = LKV_ / 64;
    for (int t = 0; t < ntiles; ++t) {
        __syncthreads();  // guard smem reuse from previous iteration

        // load K (swizzled transpose) and V (natural) tiles
        {
            const int d4 = (tid & 15) * 4;
            const int k0 = tid >> 4;
#pragma unroll
            for (int p = 0; p < 4; ++p) {
                const int kv = k0 + p * 16;
                const size_t goff = (size_t)(t * 64 + kv) * DM + d4;
                float4 kvv = *(const float4*)(Kg + goff);
                Ks[KIDX(d4 + 0, kv)] = kvv.x;
                Ks[KIDX(d4 + 1, kv)] = kvv.y;
                Ks[KIDX(d4 + 2, kv)] = kvv.z;
                Ks[KIDX(d4 + 3, kv)] = kvv.w;
                float4 vvv = *(const float4*)(Vg + goff);
                *(float4*)(Vs + kv * QPAD + d4) = vvv;
            }
        }
        __syncthreads();

        // S = Q @ K^T  (per-thread 4x4)
        float s[4][4];
#pragma unroll
        for (int i = 0; i < 4; ++i)
#pragma unroll
            for (int j = 0; j < 4; ++j) s[i][j] = 0.f;

#pragma unroll 8
        for (int dd = 0; dd < 64; ++dd) {
            float a0 = Qs[(4 * ty + 0) * QPAD + dd];
            float a1 = Qs[(4 * ty + 1) * QPAD + dd];
            float a2 = Qs[(4 * ty + 2) * QPAD + dd];
            float a3 = Qs[(4 * ty + 3) * QPAD + dd];
            float4 bb = *(const float4*)(Ks + dd * 64 + (((tx ^ (dd >> 2)) & 15) << 2));
            s[0][0] = fmaf(a0, bb.x, s[0][0]); s[0][1] = fmaf(a0, bb.y, s[0][1]);
            s[0][2] = fmaf(a0, bb.z, s[0][2]); s[0][3] = fmaf(a0, bb.w, s[0][3]);
            s[1][0] = fmaf(a1, bb.x, s[1][0]); s[1][1] = fmaf(a1, bb.y, s[1][1]);
            s[1][2] = fmaf(a1, bb.z, s[1][2]); s[1][3] = fmaf(a1, bb.w, s[1][3]);
            s[2][0] = fmaf(a2, bb.x, s[2][0]); s[2][1] = fmaf(a2, bb.y, s[2][1]);
            s[2][2] = fmaf(a2, bb.z, s[2][2]); s[2][3] = fmaf(a2, bb.w, s[2][3]);
            s[3][0] = fmaf(a3, bb.x, s[3][0]); s[3][1] = fmaf(a3, bb.y, s[3][1]);
            s[3][2] = fmaf(a3, bb.z, s[3][2]); s[3][3] = fmaf(a3, bb.w, s[3][3]);
        }
#pragma unroll
        for (int i = 0; i < 4; ++i) {
            float4 sv = make_float4(s[i][0], s[i][1], s[i][2], s[i][3]);
            *(float4*)(Ss + (4 * ty + i) * QPAD + 4 * tx) = sv;
        }
        __syncthreads();

        // online softmax: each warp owns 8 rows
#pragma unroll
        for (int rr = 0; rr < 8; ++rr) {
            const int row = wrp * 8 + rr;
            float v0 = Ss[row * QPAD + lane];
            float v1 = Ss[row * QPAD + 32 + lane];
            float mx = fmaxf(v0, v1);
#pragma unroll
            for (int off = 16; off > 0; off >>= 1)
                mx = fmaxf(mx, __shfl_xor_sync(0xffffffffu, mx, off));
            const float mold = m_s[row];
            const float mnew = fmaxf(mold, mx);
            const float p0 = __expf(v0 - mnew);
            const float p1 = __expf(v1 - mnew);
            Ss[row * QPAD + lane]      = p0;
            Ss[row * QPAD + 32 + lane] = p1;
            float sum = p0 + p1;
#pragma unroll
            for (int off = 16; off > 0; off >>= 1)
                sum += __shfl_xor_sync(0xffffffffu, sum, off);
            if (lane == 0) {
                const float c = __expf(mold - mnew);
                c_s[row] = c;
                l_s[row] = l_s[row] * c + sum;
                m_s[row] = mnew;
            }
        }
        __syncthreads();

        // rescale O and accumulate P @ V
        {
            const float c0 = c_s[4 * ty + 0];
            const float c1 = c_s[4 * ty + 1];
            const float c2 = c_s[4 * ty + 2];
            const float c3 = c_s[4 * ty + 3];
#pragma unroll
            for (int j = 0; j < 4; ++j) {
                o[0][j] *= c0; o[1][j] *= c1; o[2][j] *= c2; o[3][j] *= c3;
            }
        }
#pragma unroll 8
        for (int k = 0; k < 64; ++k) {
            float a0 = Ss[(4 * ty + 0) * QPAD + k];
            float a1 = Ss[(4 * ty + 1) * QPAD + k];
            float a2 = Ss[(4 * ty + 2) * QPAD + k];
            float a3 = Ss[(4 * ty + 3) * QPAD + k];
            float4 bb = *(const float4*)(Vs + k * QPAD + 4 * tx);
            o[0][0] = fmaf(a0, bb.x, o[0][0]); o[0][1] = fmaf(a0, bb.y, o[0][1]);
            o[0][2] = fmaf(a0, bb.z, o[0][2]); o[0][3] = fmaf(a0, bb.w, o[0][3]);
            o[1][0] = fmaf(a1, bb.x, o[1][0]); o[1][1] = fmaf(a1, bb.y, o[1][1]);
            o[1][2] = fmaf(a1, bb.z, o[1][2]); o[1][3] = fmaf(a1, bb.w, o[1][3]);
            o[2][0] = fmaf(a2, bb.x, o[2][0]); o[2][1] = fmaf(a2, bb.y, o[2][1]);
            o[2][2] = fmaf(a2, bb.z, o[2][2]); o[2][3] = fmaf(a2, bb.w, o[2][3]);
            o[3][0] = fmaf(a3, bb.x, o[3][0]); o[3][1] = fmaf(a3, bb.y, o[3][1]);
            o[3][2] = fmaf(a3, bb.z, o[3][2]); o[3][3] = fmaf(a3, bb.w, o[3][3]);
        }
    }

    // epilogue: normalize and write concat layout
#pragma unroll
    for (int i = 0; i < 4; ++i) {
        const int r   = 4 * ty + i;
        const float inv = 1.0f / l_s[r];
        float4 ov = make_float4(o[i][0] * inv, o[i][1] * inv,
                                o[i][2] * inv, o[i][3] * inv);
        *(float4*)(Ao + ((size_t)(b * LQ_ + q0 + r)) * DM + h * DK_ + 4 * tx) = ov;
    }
}

// ---------------------------------------------------------------------------
// Launch
// ---------------------------------------------------------------------------
extern "C" void kernel_launch(void* const* d_in, const int* in_sizes, int n_in,
                              void* d_out, int out_size)
{
    const float* q  = (const float*)d_in[0];
    const float* k  = (const float*)d_in[1];
    const float* v  = (const float*)d_in[2];
    const float* Wq = (const float*)d_in[3];
    const float* bq = (const float*)d_in[4];
    const float* Wk = (const float*)d_in[5];
    const float* bk = (const float*)d_in[6];
    const float* Wv = (const float*)d_in[7];
    const float* bv = (const float*)d_in[8];
    const float* Wo = (const float*)d_in[9];
    const float* bo = (const float*)d_in[10];
    float* out = (float*)d_out;

    float *Qp, *Kp, *Vp, *Ao;
    cudaGetSymbolAddress((void**)&Qp, g_Qp);
    cudaGetSymbolAddress((void**)&Kp, g_Kp);
    cudaGetSymbolAddress((void**)&Vp, g_Vp);
    cudaGetSymbolAddress((void**)&Ao, g_Ao);

    cudaFuncSetAttribute(attn_kernel,
                         cudaFuncAttributeMaxDynamicSharedMemorySize,
                         SMEM_ATTN_BYTES);

    const dim3 blk(256);

    // Q projection: [16384,1024] = q @ Wq + bq
    gemm_bias_kernel<<<dim3(DM / 128, (B_ * LQ_) / 128), blk>>>(
        q, Wq, bq, Qp, B_ * LQ_, DM, DM);
    // K projection: [8192,1024] = k @ Wk + bk   (K-dim = 512)
    gemm_bias_kernel<<<dim3(DM / 128, (B_ * LKV_) / 128), blk>>>(
        k, Wk, bk, Kp, B_ * LKV_, DM, IM);
    // V projection
    gemm_bias_kernel<<<dim3(DM / 128, (B_ * LKV_) / 128), blk>>>(
        v, Wv, bv, Vp, B_ * LKV_, DM, IM);

    // fused attention -> concat layout
    attn_kernel<<<dim3(LQ_ / 64, H_, B_), blk, SMEM_ATTN_BYTES>>>(Qp, Kp, Vp, Ao);

    // output projection -> d_out
    gemm_bias_kernel<<<dim3(DM / 128, (B_ * LQ_) / 128), blk>>>(
        Ao, Wo, bo, out, B_ * LQ_, DM, DM);
}

// round 7
// speedup vs baseline: 1.0010x; 1.0007x over previous
#include <cuda_runtime.h>

// Problem constants (fixed by setup_inputs)
#define B_    8
#define LQ_   2048
#define LKV_  1024
#define DM    1024
#define IM    512
#define H_    16
#define DK_   64

// ---------------------------------------------------------------------------
// Scratch (device globals; no allocation allowed)
// ---------------------------------------------------------------------------
__device__ float g_Qp[(size_t)B_ * LQ_ * DM];   // projected Q  [B*LQ, 1024]
__device__ float g_Kp[(size_t)B_ * LKV_ * DM];  // projected K  [B*LKV, 1024]
__device__ float g_Vp[(size_t)B_ * LKV_ * DM];  // projected V  [B*LKV, 1024]
__device__ float g_Ao[(size_t)B_ * LQ_ * DM];   // attention out (concat layout)

// ---------------------------------------------------------------------------
// GEMM + bias:  C[M,N] = A[M,K] @ W[K,N] + bias[N]
// 128x128x16 tiles, 256 threads, 8x8 per-thread register tile,
// register prefetch of next K-tile.
// Requires M%128==0, N%128==0, K%16==0 (true for all our shapes).
// ---------------------------------------------------------------------------
__global__ __launch_bounds__(256)
void gemm_bias_kernel(const float* __restrict__ A,
                      const float* __restrict__ W,
                      const float* __restrict__ bias,
                      float* __restrict__ C,
                      int M, int N, int K)
{
    __shared__ float As[16][132];   // A tile transposed [k][m], +4 pad
    __shared__ float Bs[16][128];   // W tile natural    [k][n]

    const int tid = threadIdx.x;
    const int tx  = tid & 15;       // 0..15 -> 8 cols each
    const int ty  = tid >> 4;       // 0..15 -> 8 rows each

    const int n0 = blockIdx.x * 128;
    const int m0 = blockIdx.y * 128;

    const float* Ab = A + (size_t)m0 * K;
    const float* Wb = W + n0;

    // Load mapping
    const int arow = tid >> 2;          // 0..63
    const int ak4  = (tid & 3) * 4;     // 0,4,8,12
    const int bk   = tid >> 5;          // 0..7
    const int bn4  = (tid & 31) * 4;    // 0..124

    float4 ra0, ra1, rb0, rb1;

    // prefetch tile 0
    ra0 = *(const float4*)(Ab + (size_t)arow       * K + ak4);
    ra1 = *(const float4*)(Ab + (size_t)(arow + 64) * K + ak4);
    rb0 = *(const float4*)(Wb + (size_t)bk       * N + bn4);
    rb1 = *(const float4*)(Wb + (size_t)(bk + 8) * N + bn4);

    float acc[8][8];
#pragma unroll
    for (int i = 0; i < 8; ++i)
#pragma unroll
        for (int j = 0; j < 8; ++j) acc[i][j] = 0.f;

    const int T = K / 16;
    for (int t = 0; t < T; ++t) {
        // store prefetched tile to smem
        As[ak4 + 0][arow]      = ra0.x;
        As[ak4 + 1][arow]      = ra0.y;
        As[ak4 + 2][arow]      = ra0.z;
        As[ak4 + 3][arow]      = ra0.w;
        As[ak4 + 0][arow + 64] = ra1.x;
        As[ak4 + 1][arow + 64] = ra1.y;
        As[ak4 + 2][arow + 64] = ra1.z;
        As[ak4 + 3][arow + 64] = ra1.w;
        *(float4*)&Bs[bk][bn4]     = rb0;
        *(float4*)&Bs[bk + 8][bn4] = rb1;
        __syncthreads();

        // prefetch next tile (global loads overlap compute)
        if (t + 1 < T) {
            const int k0 = (t + 1) * 16;
            ra0 = *(const float4*)(Ab + (size_t)arow       * K + k0 + ak4);
            ra1 = *(const float4*)(Ab + (size_t)(arow + 64) * K + k0 + ak4);
            rb0 = *(const float4*)(Wb + (size_t)(k0 + bk)     * N + bn4);
            rb1 = *(const float4*)(Wb + (size_t)(k0 + bk + 8) * N + bn4);
        }

        float a[8], bb[8];
#pragma unroll
        for (int kk = 0; kk < 16; ++kk) {
            *(float4*)&a[0]  = *(const float4*)&As[kk][ty * 8];
            *(float4*)&a[4]  = *(const float4*)&As[kk][ty * 8 + 4];
            *(float4*)&bb[0] = *(const float4*)&Bs[kk][tx * 8];
            *(float4*)&bb[4] = *(const float4*)&Bs[kk][tx * 8 + 4];
#pragma unroll
            for (int i = 0; i < 8; ++i)
#pragma unroll
                for (int j = 0; j < 8; ++j)
                    acc[i][j] = fmaf(a[i], bb[j], acc[i][j]);
        }
        __syncthreads();
    }

    // epilogue: bias + store
    const int crow = m0 + ty * 8;
    const int ccol = n0 + tx * 8;
    float bv[8];
#pragma unroll
    for (int j = 0; j < 8; ++j) bv[j] = bias[ccol + j];

#pragma unroll
    for (int i = 0; i < 8; ++i) {
        float4 o0, o1;
        o0.x = acc[i][0] + bv[0];
        o0.y = acc[i][1] + bv[1];
        o0.z = acc[i][2] + bv[2];
        o0.w = acc[i][3] + bv[3];
        o1.x = acc[i][4] + bv[4];
        o1.y = acc[i][5] + bv[5];
        o1.z = acc[i][6] + bv[6];
        o1.w = acc[i][7] + bv[7];
        float* cp = C + (size_t)(crow + i) * N + ccol;
        *(float4*)cp       = o0;
        *(float4*)(cp + 4) = o1;
    }
}

// ---------------------------------------------------------------------------
// Fused flash attention per (b, h, 64-row q-tile).
// Layouts: Qp/Kp/Vp are [B*L, 1024]; head h occupies cols h*64..h*64+63.
// Output written to g_Ao in concat layout [B*LQ, 1024].
// ---------------------------------------------------------------------------
#define QPAD 68
// XOR-swizzled K^T store: element (d, kv) of the 64x64 tile
#define KIDX(d, kv) ((d) * 64 + (((((kv) >> 2) ^ ((d) >> 2)) & 15) << 2) + ((kv) & 3))

#define SMEM_ATTN_FLOATS (64*QPAD /*Qs*/ + 64*64 /*Ks*/ + 64*QPAD /*Vs*/ + 64*QPAD /*Ss*/ + 3*64)
#define SMEM_ATTN_BYTES  (SMEM_ATTN_FLOATS * 4)

__global__ __launch_bounds__(256)
void attn_kernel(const float* __restrict__ Qp,
                 const float* __restrict__ Kp,
                 const float* __restrict__ Vp,
                 float* __restrict__ Ao)
{
    extern __shared__ float sm[];
    float* Qs  = sm;                    // [64][QPAD], pre-scaled by 1/8
    float* Ks  = Qs + 64 * QPAD;        // swizzled K^T: [d][kv]
    float* Vs  = Ks + 64 * 64;          // [kv][QPAD]
    float* Ss  = Vs + 64 * QPAD;        // scores / probs [row][QPAD]
    float* m_s = Ss + 64 * QPAD;        // running max  [64]
    float* l_s = m_s + 64;              // running sum  [64]
    float* c_s = l_s + 64;              // per-tile rescale [64]

    const int tid  = threadIdx.x;
    const int tx   = tid & 15;          // 0..15 : 4 cols each
    const int ty   = tid >> 4;          // 0..15 : 4 rows each
    const int lane = tid & 31;
    const int wrp  = tid >> 5;

    const int h  = blockIdx.y;
    const int b  = blockIdx.z;
    const int q0 = blockIdx.x * 64;

    const float* Qg = Qp + ((size_t)(b * LQ_ + q0)) * DM + h * DK_;
    const float* Kg = Kp + ((size_t)b * LKV_) * DM + h * DK_;
    const float* Vg = Vp + ((size_t)b * LKV_) * DM + h * DK_;

    const float scale = 0.125f;  // 1/sqrt(64)

    // load Q tile (scaled)
    {
        const int d4 = (tid & 15) * 4;
        const int r0 = tid >> 4;
#pragma unroll
        for (int p = 0; p < 4; ++p) {
            const int row = r0 + p * 16;
            float4 v = *(const float4*)(Qg + (size_t)row * DM + d4);
            v.x *= scale; v.y *= scale; v.z *= scale; v.w *= scale;
            *(float4*)(Qs + row * QPAD + d4) = v;
        }
    }
    if (tid < 64) { m_s[tid] = -1e30f; l_s[tid] = 0.f; }

    float o[4][4];
#pragma unroll
    for (int i = 0; i < 4; ++i)
#pragma unroll
        for (int j = 0; j < 4; ++j) o[i][j] = 0.f;

    const int ntiles = LKV_ / 64;
    for (int t = 0; t < ntiles; ++t) {
        __syncthreads();  // guard smem reuse from previous iteration

        // load K (swizzled transpose) and V (natural) tiles
        {
            const int d4 = (tid & 15) * 4;
            const int k0 = tid >> 4;
#pragma unroll
            for (int p = 0; p < 4; ++p) {
                const int kv = k0 + p * 16;
                const size_t goff = (size_t)(t * 64 + kv) * DM + d4;
                float4 kvv = *(const float4*)(Kg + goff);
                Ks[KIDX(d4 + 0, kv)] = kvv.x;
                Ks[KIDX(d4 + 1, kv)] = kvv.y;
                Ks[KIDX(d4 + 2, kv)] = kvv.z;
                Ks[KIDX(d4 + 3, kv)] = kvv.w;
                float4 vvv = *(const float4*)(Vg + goff);
                *(float4*)(Vs + kv * QPAD + d4) = vvv;
            }
        }
        __syncthreads();

        // S = Q @ K^T  (per-thread 4x4)
        float s[4][4];
#pragma unroll
        for (int i = 0; i < 4; ++i)
#pragma unroll
            for (int j = 0; j < 4; ++j) s[i][j] = 0.f;

#pragma unroll 8
        for (int dd = 0; dd < 64; ++dd) {
            float a0 = Qs[(4 * ty + 0) * QPAD + dd];
            float a1 = Qs[(4 * ty + 1) * QPAD + dd];
            float a2 = Qs[(4 * ty + 2) * QPAD + dd];
            float a3 = Qs[(4 * ty + 3) * QPAD + dd];
            float4 bb = *(const float4*)(Ks + dd * 64 + (((tx ^ (dd >> 2)) & 15) << 2));
            s[0][0] = fmaf(a0, bb.x, s[0][0]); s[0][1] = fmaf(a0, bb.y, s[0][1]);
            s[0][2] = fmaf(a0, bb.z, s[0][2]); s[0][3] = fmaf(a0, bb.w, s[0][3]);
            s[1][0] = fmaf(a1, bb.x, s[1][0]); s[1][1] = fmaf(a1, bb.y, s[1][1]);
            s[1][2] = fmaf(a1, bb.z, s[1][2]); s[1][3] = fmaf(a1, bb.w, s[1][3]);
            s[2][0] = fmaf(a2, bb.x, s[2][0]); s[2][1] = fmaf(a2, bb.y, s[2][1]);
            s[2][2] = fmaf(a2, bb.z, s[2][2]); s[2][3] = fmaf(a2, bb.w, s[2][3]);
            s[3][0] = fmaf(a3, bb.x, s[3][0]); s[3][1] = fmaf(a3, bb.y, s[3][1]);
            s[3][2] = fmaf(a3, bb.z, s[3][2]); s[3][3] = fmaf(a3, bb.w, s[3][3]);
        }
#pragma unroll
        for (int i = 0; i < 4; ++i) {
            float4 sv = make_float4(s[i][0], s[i][1], s[i][2], s[i][3]);
            *(float4*)(Ss + (4 * ty + i) * QPAD + 4 * tx) = sv;
        }
        __syncthreads();

        // online softmax: each warp owns 8 rows
#pragma unroll
        for (int rr = 0; rr < 8; ++rr) {
            const int row = wrp * 8 + rr;
            float v0 = Ss[row * QPAD + lane];
            float v1 = Ss[row * QPAD + 32 + lane];
            float mx = fmaxf(v0, v1);
#pragma unroll
            for (int off = 16; off > 0; off >>= 1)
                mx = fmaxf(mx, __shfl_xor_sync(0xffffffffu, mx, off));
            const float mold = m_s[row];
            const float mnew = fmaxf(mold, mx);
            const float p0 = __expf(v0 - mnew);
            const float p1 = __expf(v1 - mnew);
            Ss[row * QPAD + lane]      = p0;
            Ss[row * QPAD + 32 + lane] = p1;
            float sum = p0 + p1;
#pragma unroll
            for (int off = 16; off > 0; off >>= 1)
                sum += __shfl_xor_sync(0xffffffffu, sum, off);
            if (lane == 0) {
                const float c = __expf(mold - mnew);
                c_s[row] = c;
                l_s[row] = l_s[row] * c + sum;
                m_s[row] = mnew;
            }
        }
        __syncthreads();

        // rescale O and accumulate P @ V
        {
            const float c0 = c_s[4 * ty + 0];
            const float c1 = c_s[4 * ty + 1];
            const float c2 = c_s[4 * ty + 2];
            const float c3 = c_s[4 * ty + 3];
#pragma unroll
            for (int j = 0; j < 4; ++j) {
                o[0][j] *= c0; o[1][j] *= c1; o[2][j] *= c2; o[3][j] *= c3;
            }
        }
#pragma unroll 8
        for (int k = 0; k < 64; ++k) {
            float a0 = Ss[(4 * ty + 0) * QPAD + k];
            float a1 = Ss[(4 * ty + 1) * QPAD + k];
            float a2 = Ss[(4 * ty + 2) * QPAD + k];
            float a3 = Ss[(4 * ty + 3) * QPAD + k];
            float4 bb = *(const float4*)(Vs + k * QPAD + 4 * tx);
            o[0][0] = fmaf(a0, bb.x, o[0][0]); o[0][1] = fmaf(a0, bb.y, o[0][1]);
            o[0][2] = fmaf(a0, bb.z, o[0][2]); o[0][3] = fmaf(a0, bb.w, o[0][3]);
            o[1][0] = fmaf(a1, bb.x, o[1][0]); o[1][1] = fmaf(a1, bb.y, o[1][1]);
            o[1][2] = fmaf(a1, bb.z, o[1][2]); o[1][3] = fmaf(a1, bb.w, o[1][3]);
            o[2][0] = fmaf(a2, bb.x, o[2][0]); o[2][1] = fmaf(a2, bb.y, o[2][1]);
            o[2][2] = fmaf(a2, bb.z, o[2][2]); o[2][3] = fmaf(a2, bb.w, o[2][3]);
            o[3][0] = fmaf(a3, bb.x, o[3][0]); o[3][1] = fmaf(a3, bb.y, o[3][1]);
            o[3][2] = fmaf(a3, bb.z, o[3][2]); o[3][3] = fmaf(a3, bb.w, o[3][3]);
        }
    }

    // epilogue: normalize and write concat layout
#pragma unroll
    for (int i = 0; i < 4; ++i) {
        const int r   = 4 * ty + i;
        const float inv = 1.0f / l_s[r];
        float4 ov = make_float4(o[i][0] * inv, o[i][1] * inv,
                                o[i][2] * inv, o[i][3] * inv);
        *(float4*)(Ao + ((size_t)(b * LQ_ + q0 + r)) * DM + h * DK_ + 4 * tx) = ov;
    }
}

// ---------------------------------------------------------------------------
// Launch
// ---------------------------------------------------------------------------
extern "C" void kernel_launch(void* const* d_in, const int* in_sizes, int n_in,
                              void* d_out, int out_size)
{
    const float* q  = (const float*)d_in[0];
    const float* k  = (const float*)d_in[1];
    const float* v  = (const float*)d_in[2];
    const float* Wq = (const float*)d_in[3];
    const float* bq = (const float*)d_in[4];
    const float* Wk = (const float*)d_in[5];
    const float* bk = (const float*)d_in[6];
    const float* Wv = (const float*)d_in[7];
    const float* bv = (const float*)d_in[8];
    const float* Wo = (const float*)d_in[9];
    const float* bo = (const float*)d_in[10];
    float* out = (float*)d_out;

    float *Qp, *Kp, *Vp, *Ao;
    cudaGetSymbolAddress((void**)&Qp, g_Qp);
    cudaGetSymbolAddress((void**)&Kp, g_Kp);
    cudaGetSymbolAddress((void**)&Vp, g_Vp);
    cudaGetSymbolAddress((void**)&Ao, g_Ao);

    cudaFuncSetAttribute(attn_kernel,
                         cudaFuncAttributeMaxDynamicSharedMemorySize,
                         SMEM_ATTN_BYTES);

    const dim3 blk(256);

    // Q projection: [16384,1024] = q @ Wq + bq
    gemm_bias_kernel<<<dim3(DM / 128, (B_ * LQ_) / 128), blk>>>(
        q, Wq, bq, Qp, B_ * LQ_, DM, DM);
    // K projection: [8192,1024] = k @ Wk + bk   (K-dim = 512)
    gemm_bias_kernel<<<dim3(DM / 128, (B_ * LKV_) / 128), blk>>>(
        k, Wk, bk, Kp, B_ * LKV_, DM, IM);
    // V projection
    gemm_bias_kernel<<<dim3(DM / 128, (B_ * LKV_) / 128), blk>>>(
        v, Wv, bv, Vp, B_ * LKV_, DM, IM);

    // fused attention -> concat layout
    attn_kernel<<<dim3(LQ_ / 64, H_, B_), blk, SMEM_ATTN_BYTES>>>(Qp, Kp, Vp, Ao);

    // output projection -> d_out
    gemm_bias_kernel<<<dim3(DM / 128, (B_ * LQ_) / 128), blk>>>(
        Ao, Wo, bo, out, B_ * LQ_, DM, DM);
}